// round 14
// baseline (speedup 1.0000x reference)
#include <cuda_runtime.h>
#include <stdint.h>

#define MP1 524288
#define NXP 32768
#define PP  128
#define HT  128
#define HE  64
#define ROW_F4 (MP1 / 4)                       // 131072

// k_TE config
#define TPB_TE 1024
#define GRID_TE 148
#define PTS_TE 10
#define STRIDE_TE (GRID_TE * PTS_TE)           // 1480
#define ITERS_TE 23
#define NJET (PTS_TE * 128)                    // 1280

// scratch
__device__ float g_part[2][PP];
__device__ float g_c[PP + 1];                  // c[0..127], d0 at [128]

__device__ __forceinline__ void jet3(float z, float& T, float& s, float& d2, float& d3) {
    T  = tanhf(z);
    s  = 1.f - T * T;
    d2 = -2.f * T * s;
    d3 = -2.f * s * (1.f - 3.f * T * T);
}
__device__ __forceinline__ uint32_t f2tf(float f) {
    uint32_t u;
    asm("cvt.rna.tf32.f32 %0, %1;" : "=r"(u) : "f"(f));
    return u;
}
__device__ __forceinline__ void mma8(float* c, const uint32_t* a,
                                     uint32_t b0, uint32_t b1) {
    asm("mma.sync.aligned.m16n8k8.row.col.f32.tf32.tf32.f32 "
        "{%0,%1,%2,%3},{%4,%5,%6,%7},{%8,%9},{%0,%1,%2,%3};"
        : "+f"(c[0]), "+f"(c[1]), "+f"(c[2]), "+f"(c[3])
        : "r"(a[0]), "r"(a[1]), "r"(a[2]), "r"(a[3]), "r"(b0), "r"(b1));
}

// ================================================================ k_branch
// (R3-proven: 47.8us) grid 256: p = blockIdx&127, half = blockIdx>>7.
__global__ __launch_bounds__(1024, 2) void k_branch(const float* __restrict__ Wb,
                                                    const float* __restrict__ a,
                                                    const float* __restrict__ bb) {
    const int p = blockIdx.x & 127, half = blockIdx.x >> 7;
    const int base = half * (MP1 / 8);
    const float4* row = reinterpret_cast<const float4*>(Wb + (size_t)p * MP1) + base;
    const float4* a4  = reinterpret_cast<const float4*>(a) + base;
    float s = 0.f;
#pragma unroll 8
    for (int i = threadIdx.x; i < MP1 / 8; i += 1024) {
        float4 w = row[i], v = a4[i];
        s += w.x * v.x + w.y * v.y + w.z * v.z + w.w * v.w;
    }
    __shared__ float red[32];
    for (int o = 16; o; o >>= 1) s += __shfl_down_sync(0xffffffffu, s, o);
    if ((threadIdx.x & 31) == 0) red[threadIdx.x >> 5] = s;
    __syncthreads();
    if (threadIdx.x < 32) {
        float v = red[threadIdx.x];
        for (int o = 16; o; o >>= 1) v += __shfl_down_sync(0xffffffffu, v, o);
        if (threadIdx.x == 0) g_part[half][p] = v + (half == 0 ? bb[p] : 0.f);
    }
}

// ================================================================= k_coeff
__global__ void k_coeff(const float* __restrict__ Wt3, const float* __restrict__ bt3) {
    __shared__ float sb[PP];
    __shared__ float w4[4];
    int k = threadIdx.x;
    sb[k] = g_part[0][k] + g_part[1][k];
    __syncthreads();
    float s = 0.f;
#pragma unroll 8
    for (int p = 0; p < PP; ++p) s += sb[p] * Wt3[p * PP + k];
    g_c[k] = s;
    float v = sb[k] * bt3[k];
    for (int o = 16; o; o >>= 1) v += __shfl_down_sync(0xffffffffu, v, o);
    if ((k & 31) == 0) w4[k >> 5] = v;
    __syncthreads();
    if (k == 0) g_c[PP] = w4[0] + w4[1] + w4[2] + w4[3];
}

// ================================================================= k_TE
// smem float offsets
#define T_W0  0
#define T_ZC  128
#define T_BT2 256
#define T_C   384
#define T_P   512
#define T_Q   576
#define T_BE1 640
#define T_BE2 704
#define T_W3  768
#define T_D0  832
#define T_W1  840
#define T_W2  (T_W1 + 128 * 132)               // 17736
#define T_H1  (T_W2 + 128 * 132)               // 34632
#define T_H2  (T_H1 + 128 * 44)                // 40264
#define T_WE2 (T_H2 + 128 * 44)                // 45896
#define T_DE  (T_WE2 + 64 * 65)                // 50056
#define TE_SMEM (T_DE + 40 * 145)              // 55856 -> 223424 B

__global__ __launch_bounds__(TPB_TE, 1) void k_TE(
    const float* __restrict__ x,  const float* __restrict__ tptr,
    const float* __restrict__ Wt1, const float* __restrict__ bt1,
    const float* __restrict__ Wt2, const float* __restrict__ bt2,
    const float* __restrict__ We1, const float* __restrict__ be1,
    const float* __restrict__ We2, const float* __restrict__ be2,
    const float* __restrict__ We3, float* __restrict__ out)
{
    extern __shared__ float sm[];
    const int tid  = threadIdx.x;
    const int w    = tid >> 5;
    const int lane = tid & 31;

    // ---- stage all weights + constants
    {
        float tv = *tptr;
        if (tid < 128) {
            float w0 = Wt1[2 * tid];
            sm[T_W0 + tid]  = w0;
            sm[T_ZC + tid]  = Wt1[2 * tid + 1] * tv + bt1[tid];
            sm[T_BT2 + tid] = bt2[tid];
            sm[T_C + tid]   = g_c[tid];
        }
        if (tid < 64) {
            sm[T_P + tid]   = We1[2 * tid];
            sm[T_Q + tid]   = We1[2 * tid + 1];
            sm[T_BE1 + tid] = be1[tid];
            sm[T_BE2 + tid] = be2[tid];
            sm[T_W3 + tid]  = We3[tid];
        }
        if (tid == 0) sm[T_D0] = g_c[PP];
#pragma unroll 4
        for (int i = tid; i < HT * HT; i += TPB_TE) {
            int m = i >> 7, k = i & 127;
            float f  = Wt2[i];
            float hi = __uint_as_float(f2tf(f));
            float lo = __uint_as_float(f2tf(f - hi));
            sm[T_W1 + m * 132 + k] = hi;
            sm[T_W2 + m * 132 + k] = lo;
        }
#pragma unroll 2
        for (int i = tid; i < HE * HE; i += TPB_TE) {
            int m = i >> 6, k = i & 63;
            sm[T_WE2 + m * 65 + k] = We2[i];
        }
    }
    __syncthreads();

    const uint32_t q = lane & 3, r = lane >> 2;
    const int mt  = w & 7;                      // MMA m-tile (w<16)
    const int nt0 = w >> 3;                     // base n-tile: 0 or 1
    const int nTn = (w < 8) ? 3 : 2;            // n-tiles: {nt0, nt0+2, nt0+4}
    const int pw  = w - 16;                     // scalar warp's point (w>=16)

    // ---- prologue: phase1(it=0) by all threads
    {
        const int pb = blockIdx.x * PTS_TE;
        for (int i = tid; i < NJET; i += TPB_TE) {
            const int k = i & 127, pl = i >> 7;
            const int pt = pb + pl;
            const float xi = (pt < NXP) ? x[pt] : 0.f;
            float w0 = sm[T_W0 + k];
            float T, s, d2, d3;
            jet3(fmaf(w0, xi, sm[T_ZC + k]), T, s, d2, d3);
            float w2 = w0 * w0;
            float v0 = T, v1 = s * w0, v2 = d2 * w2, v3 = d3 * w2 * w0;
            float h0 = __uint_as_float(f2tf(v0));
            float h1 = __uint_as_float(f2tf(v1));
            float h2 = __uint_as_float(f2tf(v2));
            float h3 = __uint_as_float(f2tf(v3));
            *reinterpret_cast<float4*>(&sm[T_H1 + k * 44 + 4 * pl]) =
                make_float4(h0, h1, h2, h3);
            *reinterpret_cast<float4*>(&sm[T_H2 + k * 44 + 4 * pl]) =
                make_float4(__uint_as_float(f2tf(v0 - h0)),
                            __uint_as_float(f2tf(v1 - h1)),
                            __uint_as_float(f2tf(v2 - h2)),
                            __uint_as_float(f2tf(v3 - h3)));
        }
    }
    __syncthreads();

    for (int it = 0; it <= ITERS_TE; ++it) {
        // =================== window A: MMA(it)  ||  energy(it-1) ===========
        float acc[3][4];
        if (w < 16) {
            if (it < ITERS_TE) {
#pragma unroll
                for (int j = 0; j < 3; ++j)
#pragma unroll
                    for (int i = 0; i < 4; ++i) acc[j][i] = 0.f;
                const uint32_t* W1u = reinterpret_cast<const uint32_t*>(sm + T_W1);
                const uint32_t* W2u = reinterpret_cast<const uint32_t*>(sm + T_W2);
                const uint32_t* H1u = reinterpret_cast<const uint32_t*>(sm + T_H1);
                const uint32_t* H2u = reinterpret_cast<const uint32_t*>(sm + T_H2);
                const uint32_t rA0 = (16 * mt + r) * 132;
                const uint32_t rA1 = rA0 + 8 * 132;
#pragma unroll 4
                for (int kk = 0; kk < 16; ++kk) {
                    const uint32_t k0 = kk * 8;
                    uint32_t a1[4], a2[4];
                    a1[0] = W1u[rA0 + k0 + q];     a1[1] = W1u[rA1 + k0 + q];
                    a1[2] = W1u[rA0 + k0 + 4 + q]; a1[3] = W1u[rA1 + k0 + 4 + q];
                    a2[0] = W2u[rA0 + k0 + q];     a2[1] = W2u[rA1 + k0 + q];
                    a2[2] = W2u[rA0 + k0 + 4 + q]; a2[3] = W2u[rA1 + k0 + 4 + q];
                    const uint32_t kb0 = (k0 + q) * 44 + r;
                    const uint32_t kb1 = kb0 + 4 * 44;
#pragma unroll
                    for (int j = 0; j < 3; ++j) {
                        if (j < nTn) {
                            const int nt = nt0 + 2 * j;
                            uint32_t b10 = H1u[kb0 + 8 * nt], b11 = H1u[kb1 + 8 * nt];
                            uint32_t b20 = H2u[kb0 + 8 * nt], b21 = H2u[kb1 + 8 * nt];
                            mma8(acc[j], a1, b10, b11);   // W1*H1
                            mma8(acc[j], a2, b10, b11);   // W2*H1
                            mma8(acc[j], a1, b20, b21);   // W1*H2
                        }
                    }
                }
            }
        } else if (it >= 1 && pw < PTS_TE) {
            // ---------------- full scalar chain for point (it-1, pw) -------
            const int pt = blockIdx.x * PTS_TE + (it - 1) * STRIDE_TE + pw;
            // trunk epilogue from D + c-dot
            float s0 = 0.f, s1 = 0.f, s2 = 0.f, s3 = 0.f;
#pragma unroll
            for (int u = 0; u < 4; ++u) {
                int m = lane + 32 * u;
                const float* D = &sm[T_DE + (4 * pw) * 145 + m];
                float z0 = D[0] + sm[T_BT2 + m];
                float a1 = D[145], a2 = D[290], a3 = D[435];
                float T, s, d2, d3;
                jet3(z0, T, s, d2, d3);
                float g1 = s * a1;
                float g2 = s * a2 + d2 * a1 * a1;
                float g3 = s * a3 + 3.f * d2 * a1 * a2 + d3 * a1 * a1 * a1;
                float cc = sm[T_C + m];
                s0 += cc * T; s1 += cc * g1; s2 += cc * g2; s3 += cc * g3;
            }
#pragma unroll
            for (int o = 16; o; o >>= 1) {
                s0 += __shfl_xor_sync(0xffffffffu, s0, o);
                s1 += __shfl_xor_sync(0xffffffffu, s1, o);
                s2 += __shfl_xor_sync(0xffffffffu, s2, o);
                s3 += __shfl_xor_sync(0xffffffffu, s3, o);
            }
            const float u0 = s0 + sm[T_D0], u1 = s1, u2 = s2, u3 = s3;
            // energy layer-1 jets -> E (overlays this warp's own D rows)
            float* E = &sm[T_DE + 580 * pw];
#pragma unroll
            for (int m2 = 0; m2 < 2; ++m2) {
                int e = lane + 32 * m2;
                float pp = sm[T_P + e], qq = sm[T_Q + e];
                float T, s, d2, d3;
                jet3(pp * u0 + qq * u1 + sm[T_BE1 + e], T, s, d2, d3);
                float* eb = &E[9 * e];
                eb[0] = T;            eb[1] = s * pp;       eb[2] = s * qq;
                eb[3] = d2 * pp * pp; eb[4] = d2 * pp * qq; eb[5] = d2 * qq * qq;
                eb[6] = d3 * pp * pp * qq; eb[7] = d3 * pp * qq * qq;
                eb[8] = d3 * qq * qq * qq;
            }
            __syncwarp();
            // energy layer-2 GEMV (2 rows/thread, 9 streams)
            float b0[9], b1[9];
#pragma unroll
            for (int j = 0; j < 9; ++j) { b0[j] = 0.f; b1[j] = 0.f; }
#pragma unroll 4
            for (int k = 0; k < 64; ++k) {
                float w0 = sm[T_WE2 + lane * 65 + k];
                float w1 = sm[T_WE2 + (lane + 32) * 65 + k];
                const float* Ek = &E[9 * k];
#pragma unroll
                for (int j = 0; j < 9; ++j) {
                    float ev = Ek[j];
                    b0[j] = fmaf(w0, ev, b0[j]);
                    b1[j] = fmaf(w1, ev, b1[j]);
                }
            }
            // layer-2 multivariate jet + We3 reduction
            float q0 = 0.f, q1 = 0.f, q2 = 0.f, q3 = 0.f, q4 = 0.f;
#pragma unroll
            for (int m2 = 0; m2 < 2; ++m2) {
                int o = lane + 32 * m2;
                const float* b = m2 ? b1 : b0;
                float az0  = b[0] + sm[T_BE2 + o];
                float ay   = b[1], az   = b[2];
                float ayy  = b[3], ayz  = b[4], azz = b[5];
                float ayyz = b[6], ayzz = b[7], azzz = b[8];
                float T, s, d2, d3;
                jet3(az0, T, s, d2, d3);
                float vyy  = s * ayy  + d2 * ay * ay;
                float vzz  = s * azz  + d2 * az * az;
                float vyyz = s * ayyz + d2 * (ayy * az + 2.f * ayz * ay) + d3 * ay * ay * az;
                float vyzz = s * ayzz + d2 * (azz * ay + 2.f * ayz * az) + d3 * ay * az * az;
                float vzzz = s * azzz + 3.f * d2 * azz * az + d3 * az * az * az;
                float w3 = sm[T_W3 + o];
                q0 += w3 * vyy; q1 += w3 * vzz; q2 += w3 * vyyz;
                q3 += w3 * vyzz; q4 += w3 * vzzz;
            }
#pragma unroll
            for (int o = 16; o; o >>= 1) {
                q0 += __shfl_xor_sync(0xffffffffu, q0, o);
                q1 += __shfl_xor_sync(0xffffffffu, q1, o);
                q2 += __shfl_xor_sync(0xffffffffu, q2, o);
                q3 += __shfl_xor_sync(0xffffffffu, q3, o);
                q4 += __shfl_xor_sync(0xffffffffu, q4, o);
            }
            if (lane == 0 && pt < NXP) {
                out[pt] = -q0 * u1 + q1 * u3 + q2 * u1 * u1
                        + 2.f * q3 * u1 * u2 + q4 * u2 * u2;
            }
        }
        __syncthreads();   // (A) H(it)+D(it-1) consumed

        // =================== window B: D-store(it)  ||  phase1(it+1) =======
        if (w < 16) {
            if (it < ITERS_TE) {
#pragma unroll
                for (int j = 0; j < 3; ++j) {
                    if (j < nTn) {
                        const int nt = nt0 + 2 * j;
                        int n = 8 * nt + 2 * q;
                        int m = 16 * mt + r;
                        sm[T_DE + n * 145 + m]           = acc[j][0];
                        sm[T_DE + (n + 1) * 145 + m]     = acc[j][1];
                        sm[T_DE + n * 145 + m + 8]       = acc[j][2];
                        sm[T_DE + (n + 1) * 145 + m + 8] = acc[j][3];
                    }
                }
            }
        } else if (it + 1 < ITERS_TE) {
            const int pb = blockIdx.x * PTS_TE + (it + 1) * STRIDE_TE;
            for (int i = tid - 512; i < NJET; i += 512) {
                const int k = i & 127, pl = i >> 7;
                const int pt = pb + pl;
                const float xi = (pt < NXP) ? x[pt] : 0.f;
                float w0 = sm[T_W0 + k];
                float T, s, d2, d3;
                jet3(fmaf(w0, xi, sm[T_ZC + k]), T, s, d2, d3);
                float w2 = w0 * w0;
                float v0 = T, v1 = s * w0, v2 = d2 * w2, v3 = d3 * w2 * w0;
                float h0 = __uint_as_float(f2tf(v0));
                float h1 = __uint_as_float(f2tf(v1));
                float h2 = __uint_as_float(f2tf(v2));
                float h3 = __uint_as_float(f2tf(v3));
                *reinterpret_cast<float4*>(&sm[T_H1 + k * 44 + 4 * pl]) =
                    make_float4(h0, h1, h2, h3);
                *reinterpret_cast<float4*>(&sm[T_H2 + k * 44 + 4 * pl]) =
                    make_float4(__uint_as_float(f2tf(v0 - h0)),
                                __uint_as_float(f2tf(v1 - h1)),
                                __uint_as_float(f2tf(v2 - h2)),
                                __uint_as_float(f2tf(v3 - h3)));
            }
        }
        __syncthreads();   // (B) D(it) ready; H(it+1) ready
    }
}

// ---------------------------------------------------------------- launch
extern "C" void kernel_launch(void* const* d_in, const int* in_sizes, int n_in,
                              void* d_out, int out_size) {
    const float* a   = (const float*)d_in[0];
    const float* x   = (const float*)d_in[1];
    const float* t   = (const float*)d_in[2];
    const float* Wb  = (const float*)d_in[3];
    const float* bb  = (const float*)d_in[4];
    const float* Wt1 = (const float*)d_in[5];
    const float* bt1 = (const float*)d_in[6];
    const float* Wt2 = (const float*)d_in[7];
    const float* bt2 = (const float*)d_in[8];
    const float* Wt3 = (const float*)d_in[9];
    const float* bt3 = (const float*)d_in[10];
    const float* We1 = (const float*)d_in[11];
    const float* be1 = (const float*)d_in[12];
    const float* We2 = (const float*)d_in[13];
    const float* be2 = (const float*)d_in[14];
    const float* We3 = (const float*)d_in[15];
    (void)in_sizes; (void)n_in;
    float* out = (float*)d_out; (void)out_size;

    k_branch<<<256, 1024>>>(Wb, a, bb);
    k_coeff<<<1, 128>>>(Wt3, bt3);

    size_t smem = TE_SMEM * sizeof(float);
    cudaFuncSetAttribute(k_TE, cudaFuncAttributeMaxDynamicSharedMemorySize, (int)smem);
    k_TE<<<GRID_TE, TPB_TE, smem>>>(x, t, Wt1, bt1, Wt2, bt2,
                                    We1, be1, We2, be2, We3, out);
}

// round 16
// speedup vs baseline: 1.2291x; 1.2291x over previous
#include <cuda_runtime.h>
#include <stdint.h>

#define MP1 524288
#define NXP 32768
#define PP  128
#define HT  128
#define HE  64

#define TPB_A 1024
#define TPB   512
#define WARPS 16
#define GRID_A 148
#define PTS   12
#define STRIDE_A (GRID_A * PTS)                // 1776
#define ITERS_A 19
#define NJET (PTS * 128)                       // 1536
#define ROW_F4 (MP1 / 4)                       // 131072
#define CPB ((ROW_F4 + GRID_A - 1) / GRID_A)   // 886
#define CHUNKS ((CPB + 31) / 32)               // 28

#define GRID_B 296
#define STRIDE_B (GRID_B * WARPS)              // 4736
#define ITERS_B 7

// scratch (static device arrays, no runtime alloc)
__device__ float  g_partA[PP][GRID_A];
__device__ float  g_c[PP + 1];
__device__ float4 g_jets[NXP][PP];

__device__ __forceinline__ void jet3(float z, float& T, float& s, float& d2, float& d3) {
    T  = tanhf(z);
    s  = 1.f - T * T;
    d2 = -2.f * T * s;
    d3 = -2.f * s * (1.f - 3.f * T * T);
}
__device__ __forceinline__ uint32_t f2tf(float f) {
    uint32_t u;
    asm("cvt.rna.tf32.f32 %0, %1;" : "=r"(u) : "f"(f));
    return u;
}
__device__ __forceinline__ void mma8(float* c, const uint32_t* a,
                                     uint32_t b0, uint32_t b1) {
    asm("mma.sync.aligned.m16n8k8.row.col.f32.tf32.tf32.f32 "
        "{%0,%1,%2,%3},{%4,%5,%6,%7},{%8,%9},{%0,%1,%2,%3};"
        : "+f"(c[0]), "+f"(c[1]), "+f"(c[2]), "+f"(c[3])
        : "r"(a[0]), "r"(a[1]), "r"(a[2]), "r"(a[3]), "r"(b0), "r"(b1));
}

// ================================================================= pass A
// smem float offsets (12-pt, separate D buffer, HPAD 56 >= 48 cols)
#define HPAD 56
#define OFF_W0  0
#define OFF_ZC  128
#define OFF_BT2 256
#define OFF_W1  384
#define OFF_W2  (OFF_W1 + 128 * 132)           // 17280
#define OFF_H1  (OFF_W2 + 128 * 132)           // 34176
#define OFF_H2  (OFF_H1 + 128 * HPAD)          // 41344
#define OFF_D   (OFF_H2 + 128 * HPAD)          // 48512
#define A_SMEM_FLOATS (OFF_D + 48 * 132)       // 54848 -> 219392 B

// phase1: layer-1 tanh jets -> H1/H2 (tf32 split), flat [start::stride)
__device__ __forceinline__ void phase1_range(
    float* sm, const float* __restrict__ x, int ptbase, int start, int stride)
{
    for (int i = start; i < NJET; i += stride) {
        const int k = i & 127, pl = i >> 7;
        const int pt = ptbase + pl;
        const float xi = (pt < NXP) ? x[pt] : 0.f;
        float w0 = sm[OFF_W0 + k];
        float T, s, d2, d3;
        jet3(fmaf(w0, xi, sm[OFF_ZC + k]), T, s, d2, d3);
        float w2 = w0 * w0;
        float v0 = T, v1 = s * w0, v2 = d2 * w2, v3 = d3 * w2 * w0;
        float h0 = __uint_as_float(f2tf(v0));
        float h1 = __uint_as_float(f2tf(v1));
        float h2 = __uint_as_float(f2tf(v2));
        float h3 = __uint_as_float(f2tf(v3));
        *reinterpret_cast<float4*>(&sm[OFF_H1 + k * HPAD + 4 * pl]) =
            make_float4(h0, h1, h2, h3);
        *reinterpret_cast<float4*>(&sm[OFF_H2 + k * HPAD + 4 * pl]) =
            make_float4(__uint_as_float(f2tf(v0 - h0)),
                        __uint_as_float(f2tf(v1 - h1)),
                        __uint_as_float(f2tf(v2 - h2)),
                        __uint_as_float(f2tf(v3 - h3)));
    }
}

// epilogue: tanh jets from D[n][m pad 132] -> g_jets, flat [start::stride)
__device__ __forceinline__ void epilogue_range(
    const float* sm, int ptbase, int start, int stride)
{
    for (int i = start; i < NJET; i += stride) {
        const int m = i & 127, pl = i >> 7;
        const int pt = ptbase + pl;
        if (pt >= NXP) continue;
        const float* D = sm + OFF_D + (4 * pl) * 132 + m;
        float z0 = D[0] + sm[OFF_BT2 + m];
        float a1 = D[132], a2 = D[264], a3 = D[396];
        float T, s, d2, d3;
        jet3(z0, T, s, d2, d3);
        float g1 = s * a1;
        float g2 = s * a2 + d2 * a1 * a1;
        float g3 = s * a3 + 3.f * d2 * a1 * a2 + d3 * a1 * a1 * a1;
        g_jets[pt][m] = make_float4(T, g1, g2, g3);
    }
}

__global__ __launch_bounds__(TPB_A, 1) void k_A(
    const float* __restrict__ Wb, const float* __restrict__ a,
    const float* __restrict__ x,  const float* __restrict__ tptr,
    const float* __restrict__ Wt1, const float* __restrict__ bt1,
    const float* __restrict__ Wt2, const float* __restrict__ bt2)
{
    extern __shared__ float sm[];
    const int tid  = threadIdx.x;
    const int w    = tid >> 5;
    const int lane = tid & 31;

    // ---- stage constants + Wt2 2-way tf32 split (pad 132)
    {
        float tv = *tptr;
        if (tid < 128) {
            float w0 = Wt1[2 * tid];
            sm[OFF_W0 + tid]  = w0;
            sm[OFF_ZC + tid]  = Wt1[2 * tid + 1] * tv + bt1[tid];
            sm[OFF_BT2 + tid] = bt2[tid];
        }
#pragma unroll 4
        for (int i = tid; i < HT * HT; i += TPB_A) {
            int m = i >> 7, k = i & 127;
            float f  = Wt2[i];
            float hi = __uint_as_float(f2tf(f));
            float lo = __uint_as_float(f2tf(f - hi));
            sm[OFF_W1 + m * 132 + k] = hi;
            sm[OFF_W2 + m * 132 + k] = lo;
        }
    }
    __syncthreads();

    const int colbase = blockIdx.x * CPB;
    const int colend  = min(colbase + CPB, ROW_F4);
    const float4* a4  = reinterpret_cast<const float4*>(a);
    const float4* Wb4 = reinterpret_cast<const float4*>(Wb);
    float part[8];
#pragma unroll
    for (int u = 0; u < 8; ++u) part[u] = 0.f;

    const uint32_t q = lane & 3, r = lane >> 2;
    float* Dsm = sm + OFF_D;                    // [n=48][m pad 132]
    const int mt = w >> 1, nh = w & 1;          // MMA tiles (w<16)
    const int wb = w - 16;                      // branch id (w>=16)

    // ---- prologue: phase1(it=0) by all threads
    phase1_range(sm, x, blockIdx.x * PTS, tid, TPB_A);
    __syncthreads();

    for (int it = 0; it < ITERS_A; ++it) {
        const int ptbase = blockIdx.x * PTS + it * STRIDE_A;

        // === W1: MMA(it)+D-store  ||  branch chunks ======================
        if (w < 16) {
            float c[3][4];
#pragma unroll
            for (int j = 0; j < 3; ++j)
#pragma unroll
                for (int i = 0; i < 4; ++i) c[j][i] = 0.f;

            const uint32_t* W1u = reinterpret_cast<const uint32_t*>(sm + OFF_W1);
            const uint32_t* W2u = reinterpret_cast<const uint32_t*>(sm + OFF_W2);
            const uint32_t* H1u = reinterpret_cast<const uint32_t*>(sm + OFF_H1);
            const uint32_t* H2u = reinterpret_cast<const uint32_t*>(sm + OFF_H2);
            const uint32_t rA0 = (16 * mt + r) * 132;
            const uint32_t rA1 = rA0 + 8 * 132;

#pragma unroll 4
            for (int kk = 0; kk < 16; ++kk) {
                const uint32_t k0 = kk * 8;
                uint32_t a1[4], a2[4];
                a1[0] = W1u[rA0 + k0 + q];     a1[1] = W1u[rA1 + k0 + q];
                a1[2] = W1u[rA0 + k0 + 4 + q]; a1[3] = W1u[rA1 + k0 + 4 + q];
                a2[0] = W2u[rA0 + k0 + q];     a2[1] = W2u[rA1 + k0 + q];
                a2[2] = W2u[rA0 + k0 + 4 + q]; a2[3] = W2u[rA1 + k0 + 4 + q];
                const uint32_t kb0 = (k0 + q) * HPAD + r;
                const uint32_t kb1 = kb0 + 4 * HPAD;
#pragma unroll
                for (int j = 0; j < 3; ++j) {
                    const int ntg = 3 * nh + j;
                    uint32_t b10 = H1u[kb0 + 8 * ntg], b11 = H1u[kb1 + 8 * ntg];
                    uint32_t b20 = H2u[kb0 + 8 * ntg], b21 = H2u[kb1 + 8 * ntg];
                    mma8(c[j], a1, b10, b11);   // W1*H1
                    mma8(c[j], a2, b10, b11);   // W2*H1
                    mma8(c[j], a1, b20, b21);   // W1*H2
                }
            }
            // D-store (separate buffer, no pre-barrier needed)
#pragma unroll
            for (int j = 0; j < 3; ++j) {
                const int ntg = 3 * nh + j;
                int n = 8 * ntg + 2 * q;
                int m = 16 * mt + r;
                Dsm[n * 132 + m]           = c[j][0];
                Dsm[(n + 1) * 132 + m]     = c[j][1];
                Dsm[n * 132 + m + 8]       = c[j][2];
                Dsm[(n + 1) * 132 + m + 8] = c[j][3];
            }
        } else {
#pragma unroll
            for (int j = 0; j < 2; ++j) {
                int ch = 2 * it + j;
                if (ch < CHUNKS) {
                    int cidx = colbase + ch * 32 + lane;
                    if (cidx < colend) {
                        float4 av = __ldg(a4 + cidx);
#pragma unroll
                        for (int u = 0; u < 8; ++u) {
                            const float4 wv =
                                __ldcs(Wb4 + (size_t)(wb + 16 * u) * ROW_F4 + cidx);
                            part[u] += wv.x * av.x + wv.y * av.y
                                     + wv.z * av.z + wv.w * av.w;
                        }
                    }
                }
            }
        }
        __syncthreads();   // (1) H consumed; D(it) ready

        // === W2: epilogue(it)  ||  phase1(it+1) ==========================
        if (w < 16) {
            epilogue_range(sm, ptbase, tid, 512);
        } else if (it + 1 < ITERS_A) {
            phase1_range(sm, x, ptbase + STRIDE_A, tid - 512, 512);
        }
        __syncthreads();   // (2) D consumed; H(it+1) ready
    }

    // ---- branch partials (deterministic, per-block)
    if (w >= 16) {
#pragma unroll
        for (int u = 0; u < 8; ++u) {
            float v = part[u];
#pragma unroll
            for (int o = 16; o; o >>= 1) v += __shfl_down_sync(0xffffffffu, v, o);
            if (lane == 0) g_partA[wb + 16 * u][blockIdx.x] = v;
        }
    }
}

// ======================================================== coeff: b, c, d0
__global__ void k_coeff(const float* __restrict__ Wt3, const float* __restrict__ bt3,
                        const float* __restrict__ bb) {
    __shared__ float sb[PP];
    __shared__ float w4[4];
    int k = threadIdx.x;
    float b = bb[k];
#pragma unroll 4
    for (int i = 0; i < GRID_A; ++i) b += g_partA[k][i];
    sb[k] = b;
    __syncthreads();
    float s = 0.f;
#pragma unroll 8
    for (int p = 0; p < PP; ++p) s += sb[p] * Wt3[p * PP + k];
    g_c[k] = s;
    float v = sb[k] * bt3[k];
    for (int o = 16; o; o >>= 1) v += __shfl_down_sync(0xffffffffu, v, o);
    if ((k & 31) == 0) w4[k >> 5] = v;
    __syncthreads();
    if (k == 0) g_c[PP] = w4[0] + w4[1] + w4[2] + w4[3];
}

// ================================================================= pass B
// (R9 scalar version — proven ~85us)
#define EPAD 68
#define B_WE2 0
#define B_C   4352
#define B_P   4480
#define B_Q   4544
#define B_BE1 4608
#define B_BE2 4672
#define B_W3  4736
#define B_D0  4800
#define B_E   4804
#define B_SMEM (B_E + WARPS * 768)

__global__ __launch_bounds__(TPB, 2) void k_B(
    const float* __restrict__ We1, const float* __restrict__ be1,
    const float* __restrict__ We2, const float* __restrict__ be2,
    const float* __restrict__ We3, float* __restrict__ out)
{
    extern __shared__ float sm[];
    const int tid = threadIdx.x;

    {
        const float4* se = reinterpret_cast<const float4*>(We2);
#pragma unroll
        for (int i = tid; i < HE * HE / 4; i += TPB) {
            int e = i * 4, j = e >> 6, k = e & 63;
            *reinterpret_cast<float4*>(&sm[B_WE2 + j * EPAD + k]) = se[i];
        }
        if (tid < 128) sm[B_C + tid] = g_c[tid];
        if (tid < 64) {
            sm[B_P + tid]   = We1[2 * tid];
            sm[B_Q + tid]   = We1[2 * tid + 1];
            sm[B_BE1 + tid] = be1[tid];
            sm[B_BE2 + tid] = be2[tid];
            sm[B_W3 + tid]  = We3[tid];
        }
        if (tid == 0) sm[B_D0] = g_c[PP];
    }
    __syncthreads();

    const int w    = tid >> 5;
    const int lane = tid & 31;
    float* E1 = sm + B_E + w * 768;
    const int base_pt = blockIdx.x * WARPS + w;
    const float c0 = sm[B_C + lane], c1 = sm[B_C + lane + 32];
    const float c2 = sm[B_C + lane + 64], c3 = sm[B_C + lane + 96];
    const float d0 = sm[B_D0];

    for (int it = 0; it < ITERS_B; ++it) {
        const int pt = base_pt + it * STRIDE_B;
        const bool active = pt < NXP;

        float p0, p1, p2, p3;
        {
            float4 j0, j1, j2, j3;
            if (active) {
                j0 = g_jets[pt][lane];      j1 = g_jets[pt][lane + 32];
                j2 = g_jets[pt][lane + 64]; j3 = g_jets[pt][lane + 96];
            } else {
                j0 = j1 = j2 = j3 = make_float4(0.f, 0.f, 0.f, 0.f);
            }
            p0 = c0 * j0.x + c1 * j1.x + c2 * j2.x + c3 * j3.x;
            p1 = c0 * j0.y + c1 * j1.y + c2 * j2.y + c3 * j3.y;
            p2 = c0 * j0.z + c1 * j1.z + c2 * j2.z + c3 * j3.z;
            p3 = c0 * j0.w + c1 * j1.w + c2 * j2.w + c3 * j3.w;
        }
#pragma unroll
        for (int o = 16; o; o >>= 1) {
            p0 += __shfl_xor_sync(0xffffffffu, p0, o);
            p1 += __shfl_xor_sync(0xffffffffu, p1, o);
            p2 += __shfl_xor_sync(0xffffffffu, p2, o);
            p3 += __shfl_xor_sync(0xffffffffu, p3, o);
        }
        const float u0 = p0 + d0, u1 = p1, u2 = p2, u3 = p3;

#pragma unroll
        for (int m = 0; m < 2; ++m) {
            int e = lane + 32 * m;
            float pp = sm[B_P + e], qq = sm[B_Q + e];
            float T, s, d2, d3;
            jet3(pp * u0 + qq * u1 + sm[B_BE1 + e], T, s, d2, d3);
            float* eb = &E1[12 * e];
            *reinterpret_cast<float4*>(eb) = make_float4(T, s * pp, s * qq, d2 * pp * pp);
            *reinterpret_cast<float4*>(eb + 4) =
                make_float4(d2 * pp * qq, d2 * qq * qq, d3 * pp * pp * qq, d3 * pp * qq * qq);
            eb[8] = d3 * qq * qq * qq;
        }
        __syncwarp();

        float b[2][9];
#pragma unroll
        for (int m = 0; m < 2; ++m)
#pragma unroll
            for (int s9 = 0; s9 < 9; ++s9) b[m][s9] = 0.f;
#pragma unroll 4
        for (int k4 = 0; k4 < 16; ++k4) {
            float4 wv0 = *reinterpret_cast<const float4*>(&sm[B_WE2 + lane * EPAD + 4 * k4]);
            float4 wv1 = *reinterpret_cast<const float4*>(&sm[B_WE2 + (lane + 32) * EPAD + 4 * k4]);
#pragma unroll
            for (int i = 0; i < 4; ++i) {
                const float* e = &E1[12 * (4 * k4 + i)];
                float4 eA = *reinterpret_cast<const float4*>(e);
                float4 eB = *reinterpret_cast<const float4*>(e + 4);
                float  eC = e[8];
                float wk0 = (i == 0) ? wv0.x : (i == 1) ? wv0.y : (i == 2) ? wv0.z : wv0.w;
                float wk1 = (i == 0) ? wv1.x : (i == 1) ? wv1.y : (i == 2) ? wv1.z : wv1.w;
                b[0][0] += wk0 * eA.x; b[0][1] += wk0 * eA.y; b[0][2] += wk0 * eA.z; b[0][3] += wk0 * eA.w;
                b[0][4] += wk0 * eB.x; b[0][5] += wk0 * eB.y; b[0][6] += wk0 * eB.z; b[0][7] += wk0 * eB.w;
                b[0][8] += wk0 * eC;
                b[1][0] += wk1 * eA.x; b[1][1] += wk1 * eA.y; b[1][2] += wk1 * eA.z; b[1][3] += wk1 * eA.w;
                b[1][4] += wk1 * eB.x; b[1][5] += wk1 * eB.y; b[1][6] += wk1 * eB.z; b[1][7] += wk1 * eB.w;
                b[1][8] += wk1 * eC;
            }
        }

        float q0 = 0.f, q1 = 0.f, q2 = 0.f, q3 = 0.f, q4 = 0.f;
#pragma unroll
        for (int m = 0; m < 2; ++m) {
            int o = lane + 32 * m;
            float az0  = b[m][0] + sm[B_BE2 + o];
            float ay   = b[m][1], az   = b[m][2];
            float ayy  = b[m][3], ayz  = b[m][4], azz = b[m][5];
            float ayyz = b[m][6], ayzz = b[m][7], azzz = b[m][8];
            float T, s, d2, d3;
            jet3(az0, T, s, d2, d3);
            float vyy  = s * ayy  + d2 * ay * ay;
            float vzz  = s * azz  + d2 * az * az;
            float vyyz = s * ayyz + d2 * (ayy * az + 2.f * ayz * ay) + d3 * ay * ay * az;
            float vyzz = s * ayzz + d2 * (azz * ay + 2.f * ayz * az) + d3 * ay * az * az;
            float vzzz = s * azzz + 3.f * d2 * azz * az + d3 * az * az * az;
            float w3 = sm[B_W3 + o];
            q0 += w3 * vyy; q1 += w3 * vzz; q2 += w3 * vyyz; q3 += w3 * vyzz; q4 += w3 * vzzz;
        }
#pragma unroll
        for (int o = 16; o; o >>= 1) {
            q0 += __shfl_xor_sync(0xffffffffu, q0, o);
            q1 += __shfl_xor_sync(0xffffffffu, q1, o);
            q2 += __shfl_xor_sync(0xffffffffu, q2, o);
            q3 += __shfl_xor_sync(0xffffffffu, q3, o);
            q4 += __shfl_xor_sync(0xffffffffu, q4, o);
        }
        if (lane == 0 && active) {
            out[pt] = -q0 * u1 + q1 * u3 + q2 * u1 * u1
                    + 2.f * q3 * u1 * u2 + q4 * u2 * u2;
        }
        __syncwarp();
    }
}

// ---------------------------------------------------------------- launch
extern "C" void kernel_launch(void* const* d_in, const int* in_sizes, int n_in,
                              void* d_out, int out_size) {
    const float* a   = (const float*)d_in[0];
    const float* x   = (const float*)d_in[1];
    const float* t   = (const float*)d_in[2];
    const float* Wb  = (const float*)d_in[3];
    const float* bb  = (const float*)d_in[4];
    const float* Wt1 = (const float*)d_in[5];
    const float* bt1 = (const float*)d_in[6];
    const float* Wt2 = (const float*)d_in[7];
    const float* bt2 = (const float*)d_in[8];
    const float* Wt3 = (const float*)d_in[9];
    const float* bt3 = (const float*)d_in[10];
    const float* We1 = (const float*)d_in[11];
    const float* be1 = (const float*)d_in[12];
    const float* We2 = (const float*)d_in[13];
    const float* be2 = (const float*)d_in[14];
    const float* We3 = (const float*)d_in[15];
    (void)in_sizes; (void)n_in;
    float* out = (float*)d_out; (void)out_size;

    size_t smemA = A_SMEM_FLOATS * sizeof(float);
    cudaFuncSetAttribute(k_A, cudaFuncAttributeMaxDynamicSharedMemorySize, (int)smemA);
    k_A<<<GRID_A, TPB_A, smemA>>>(Wb, a, x, t, Wt1, bt1, Wt2, bt2);

    k_coeff<<<1, 128>>>(Wt3, bt3, bb);

    size_t smemB = B_SMEM * sizeof(float);
    cudaFuncSetAttribute(k_B, cudaFuncAttributeMaxDynamicSharedMemorySize, (int)smemB);
    k_B<<<GRID_B, TPB, smemB>>>(We1, be1, We2, be2, We3, out);
}

// round 17
// speedup vs baseline: 1.5045x; 1.2241x over previous
#include <cuda_runtime.h>
#include <cuda_fp16.h>
#include <stdint.h>

#define MP1 524288
#define NXP 32768
#define PP  128
#define HT  128
#define HE  64

#define TPB_A 1024
#define TPB   512
#define WARPS 16
#define GRID_A 148
#define STRIDE_A (GRID_A * 16)                 // 2368 (16 points per block-iter)
#define ITERS_A 14
#define ROW_F4 (MP1 / 4)                       // 131072
#define CPB ((ROW_F4 + GRID_A - 1) / GRID_A)   // 886

#define GRID_B 296
#define STRIDE_B (GRID_B * WARPS)              // 4736
#define ITERS_B 7

// scratch (static device arrays, no runtime alloc)
__device__ float  g_partA[PP][GRID_A];
__device__ float  g_c[PP + 1];
__device__ float4 g_jets[NXP][PP];

__device__ __forceinline__ void jet3(float z, float& T, float& s, float& d2, float& d3) {
    T  = tanhf(z);
    s  = 1.f - T * T;
    d2 = -2.f * T * s;
    d3 = -2.f * s * (1.f - 3.f * T * T);
}
__device__ __forceinline__ uint32_t packh2(float lo, float hi) {
    __half2 h = __halves2half2(__float2half_rn(lo), __float2half_rn(hi));
    return *reinterpret_cast<uint32_t*>(&h);
}
__device__ __forceinline__ void mma16(float* c, const uint32_t* a,
                                      uint32_t b0, uint32_t b1) {
    asm("mma.sync.aligned.m16n8k16.row.col.f32.f16.f16.f32 "
        "{%0,%1,%2,%3},{%4,%5,%6,%7},{%8,%9},{%0,%1,%2,%3};"
        : "+f"(c[0]), "+f"(c[1]), "+f"(c[2]), "+f"(c[3])
        : "r"(a[0]), "r"(a[1]), "r"(a[2]), "r"(a[3]), "r"(b0), "r"(b1));
}

// ================================================================= pass A
// smem word offsets (R9 schedule; fp16-pair operand tiles)
#define OFF_W0  0
#define OFF_ZC  128
#define OFF_BT2 256
#define OFF_A1  384                            // 128*68 = 8704
#define OFF_A2  (OFF_A1 + 8704)                // 9088
#define OFF_B1  (OFF_A2 + 8704)                // 17792: 64*72 = 4608
#define OFF_B2  (OFF_B1 + 4608)                // 22400
#define OFF_D   (OFF_B2 + 4608)                // 27008: 64*132 = 8448
#define A_SMEM_FLOATS (OFF_D + 8448)           // 35456 -> 141824 B

__global__ __launch_bounds__(TPB_A, 1) void k_A(
    const float* __restrict__ Wb, const float* __restrict__ a,
    const float* __restrict__ x,  const float* __restrict__ tptr,
    const float* __restrict__ Wt1, const float* __restrict__ bt1,
    const float* __restrict__ Wt2, const float* __restrict__ bt2)
{
    extern __shared__ float sm[];
    const int tid  = threadIdx.x;
    const int w    = tid >> 5;
    const int lane = tid & 31;
    uint32_t* A1u = reinterpret_cast<uint32_t*>(sm + OFF_A1);
    uint32_t* A2u = reinterpret_cast<uint32_t*>(sm + OFF_A2);
    uint32_t* B1u = reinterpret_cast<uint32_t*>(sm + OFF_B1);
    uint32_t* B2u = reinterpret_cast<uint32_t*>(sm + OFF_B2);

    // ---- stage constants + Wt2 fp16 2-way split, packed k-pairs (pad 68)
    {
        float tv = *tptr;
        if (tid < 128) {
            float w0 = Wt1[2 * tid];
            sm[OFF_W0 + tid]  = w0;
            sm[OFF_ZC + tid]  = Wt1[2 * tid + 1] * tv + bt1[tid];
            sm[OFF_BT2 + tid] = bt2[tid];
        }
#pragma unroll 4
        for (int i = tid; i < 128 * 64; i += TPB_A) {
            int m = i >> 6, k2 = i & 63;
            float e0 = Wt2[m * 128 + 2 * k2];
            float e1 = Wt2[m * 128 + 2 * k2 + 1];
            __half h0 = __float2half_rn(e0), h1 = __float2half_rn(e1);
            A1u[m * 68 + k2] = packh2(e0, e1) /*placeholder*/;
            // overwrite with proper hi/lo packing:
            {
                __half2 ph = __halves2half2(h0, h1);
                A1u[m * 68 + k2] = *reinterpret_cast<uint32_t*>(&ph);
                __half2 pl = __halves2half2(__float2half_rn(e0 - __half2float(h0)),
                                            __float2half_rn(e1 - __half2float(h1)));
                A2u[m * 68 + k2] = *reinterpret_cast<uint32_t*>(&pl);
            }
        }
    }
    __syncthreads();

    const int colbase = blockIdx.x * CPB;
    const int colend  = min(colbase + CPB, ROW_F4);
    const float4* a4  = reinterpret_cast<const float4*>(a);
    const float4* Wb4 = reinterpret_cast<const float4*>(Wb);
    float part[8];
#pragma unroll
    for (int u = 0; u < 8; ++u) part[u] = 0.f;

    const uint32_t q = lane & 3, r = lane >> 2;
    float* Dsm = sm + OFF_D;                    // [n=64][m pad 132]
    const int p    = w & 15;
    const int half = w >> 4;
    const int mt   = w >> 1,  nh = w & 1;       // MMA tiles (w<16)
    const int wb   = w - 16;                    // branch id (w>=16)
    const int pr   = 32 * half + lane;          // phase-1 pair-row (units 2pr,2pr+1)

    for (int it = 0; it < ITERS_A; ++it) {
        const int pt0 = blockIdx.x * 16 + it * STRIDE_A;

        // ---- phase 1: layer-1 jets, packed fp16 pairs -> B1/B2
        {
            const int ptw = pt0 + p;
            const float xi = (ptw < NXP) ? x[ptw] : 0.f;
            float vA[4], vB[4];
#pragma unroll
            for (int e = 0; e < 2; ++e) {
                int k = 2 * pr + e;
                float w0 = sm[OFF_W0 + k];
                float T, s, d2, d3;
                jet3(fmaf(w0, xi, sm[OFF_ZC + k]), T, s, d2, d3);
                float w2 = w0 * w0;
                float* v = e ? vB : vA;
                v[0] = T; v[1] = s * w0; v[2] = d2 * w2; v[3] = d3 * w2 * w0;
            }
            uint32_t hi[4], lo[4];
#pragma unroll
            for (int s9 = 0; s9 < 4; ++s9) {
                __half hA = __float2half_rn(vA[s9]);
                __half hB = __float2half_rn(vB[s9]);
                __half2 ph = __halves2half2(hA, hB);
                hi[s9] = *reinterpret_cast<uint32_t*>(&ph);
                __half2 pl = __halves2half2(
                    __float2half_rn(vA[s9] - __half2float(hA)),
                    __float2half_rn(vB[s9] - __half2float(hB)));
                lo[s9] = *reinterpret_cast<uint32_t*>(&pl);
            }
            *reinterpret_cast<uint4*>(&B1u[pr * 72 + 4 * p]) =
                make_uint4(hi[0], hi[1], hi[2], hi[3]);
            *reinterpret_cast<uint4*>(&B2u[pr * 72 + 4 * p]) =
                make_uint4(lo[0], lo[1], lo[2], lo[3]);
        }
        __syncthreads();   // (1) B ready

        float c[4][4];
        if (w < 16) {
            // ---- MMA: m-tile mt (16 rows) x 4 n-tiles (half nh), 3 products
#pragma unroll
            for (int j = 0; j < 4; ++j)
#pragma unroll
                for (int i = 0; i < 4; ++i) c[j][i] = 0.f;

            const uint32_t rA0 = (16 * mt + r) * 68;
            const uint32_t rA1 = rA0 + 8 * 68;
#pragma unroll
            for (int kk = 0; kk < 8; ++kk) {
                const uint32_t k0 = 8 * kk;
                uint32_t ah[4], al[4];
                ah[0] = A1u[rA0 + k0 + q];     ah[1] = A1u[rA1 + k0 + q];
                ah[2] = A1u[rA0 + k0 + 4 + q]; ah[3] = A1u[rA1 + k0 + 4 + q];
                al[0] = A2u[rA0 + k0 + q];     al[1] = A2u[rA1 + k0 + q];
                al[2] = A2u[rA0 + k0 + 4 + q]; al[3] = A2u[rA1 + k0 + 4 + q];
                const uint32_t kb0 = (k0 + q) * 72 + r;
                const uint32_t kb1 = (k0 + q + 4) * 72 + r;
#pragma unroll
                for (int j = 0; j < 4; ++j) {
                    const int ntg = 4 * nh + j;
                    uint32_t bh0 = B1u[kb0 + 8 * ntg], bh1 = B1u[kb1 + 8 * ntg];
                    uint32_t bl0 = B2u[kb0 + 8 * ntg], bl1 = B2u[kb1 + 8 * ntg];
                    mma16(c[j], ah, bh0, bh1);   // Ahi*Bhi
                    mma16(c[j], al, bh0, bh1);   // Alo*Bhi
                    mma16(c[j], ah, bl0, bl1);   // Ahi*Blo
                }
            }
        } else {
            // ---- branch warps (16): DRAM stream, rows wb + 16u, u<8
#pragma unroll
            for (int j = 0; j < 2; ++j) {
                int cidx = colbase + (it * 2 + j) * 32 + lane;
                if (cidx < colend) {
                    float4 av = __ldg(a4 + cidx);
#pragma unroll
                    for (int u = 0; u < 8; ++u) {
                        int row = wb + 16 * u;
                        float4 wv = __ldcs(Wb4 + (size_t)row * ROW_F4 + cidx);
                        part[u] += wv.x * av.x + wv.y * av.y + wv.z * av.z + wv.w * av.w;
                    }
                }
            }
        }
        __syncthreads();   // (2) all B reads done

        if (w < 16) {      // store D = [n][m pad 132]
#pragma unroll
            for (int j = 0; j < 4; ++j) {
                const int ntg = 4 * nh + j;
                int n = 8 * ntg + 2 * q;
                int m = 16 * mt + r;
                Dsm[n * 132 + m]           = c[j][0];
                Dsm[(n + 1) * 132 + m]     = c[j][1];
                Dsm[n * 132 + m + 8]       = c[j][2];
                Dsm[(n + 1) * 132 + m + 8] = c[j][3];
            }
        }
        __syncthreads();   // (3) D ready

        // ---- epilogue: tanh jets -> g_jets (2 warps per point)
        {
            const int pt = pt0 + p;
            if (pt < NXP) {
#pragma unroll
                for (int u = 0; u < 2; ++u) {
                    int m = 64 * half + lane + 32 * u;
                    float z0 = Dsm[(4 * p + 0) * 132 + m] + sm[OFF_BT2 + m];
                    float a1 = Dsm[(4 * p + 1) * 132 + m];
                    float a2 = Dsm[(4 * p + 2) * 132 + m];
                    float a3 = Dsm[(4 * p + 3) * 132 + m];
                    float T, s, d2, d3;
                    jet3(z0, T, s, d2, d3);
                    float g1 = s * a1;
                    float g2 = s * a2 + d2 * a1 * a1;
                    float g3 = s * a3 + 3.f * d2 * a1 * a2 + d3 * a1 * a1 * a1;
                    g_jets[pt][m] = make_float4(T, g1, g2, g3);
                }
            }
        }
        __syncthreads();   // (4) D reads done before next phase-1
    }

    // ---- branch partials (deterministic, per-block)
    if (w >= 16) {
#pragma unroll
        for (int u = 0; u < 8; ++u) {
            int row = wb + 16 * u;
            float v = part[u];
#pragma unroll
            for (int o = 16; o; o >>= 1) v += __shfl_down_sync(0xffffffffu, v, o);
            if (lane == 0) g_partA[row][blockIdx.x] = v;
        }
    }
}

// ======================================================== coeff: b, c, d0
__global__ void k_coeff(const float* __restrict__ Wt3, const float* __restrict__ bt3,
                        const float* __restrict__ bb) {
    __shared__ float sb[PP];
    __shared__ float w4[4];
    int k = threadIdx.x;
    float b = bb[k];
#pragma unroll 4
    for (int i = 0; i < GRID_A; ++i) b += g_partA[k][i];
    sb[k] = b;
    __syncthreads();
    float s = 0.f;
#pragma unroll 8
    for (int p = 0; p < PP; ++p) s += sb[p] * Wt3[p * PP + k];
    g_c[k] = s;
    float v = sb[k] * bt3[k];
    for (int o = 16; o; o >>= 1) v += __shfl_down_sync(0xffffffffu, v, o);
    if ((k & 31) == 0) w4[k >> 5] = v;
    __syncthreads();
    if (k == 0) g_c[PP] = w4[0] + w4[1] + w4[2] + w4[3];
}

// ================================================================= pass B
// (R9 scalar version — proven ~85us)
#define EPAD 68
#define B_WE2 0
#define B_C   4352
#define B_P   4480
#define B_Q   4544
#define B_BE1 4608
#define B_BE2 4672
#define B_W3  4736
#define B_D0  4800
#define B_E   4804
#define B_SMEM (B_E + WARPS * 768)

__global__ __launch_bounds__(TPB, 2) void k_B(
    const float* __restrict__ We1, const float* __restrict__ be1,
    const float* __restrict__ We2, const float* __restrict__ be2,
    const float* __restrict__ We3, float* __restrict__ out)
{
    extern __shared__ float sm[];
    const int tid = threadIdx.x;

    {
        const float4* se = reinterpret_cast<const float4*>(We2);
#pragma unroll
        for (int i = tid; i < HE * HE / 4; i += TPB) {
            int e = i * 4, j = e >> 6, k = e & 63;
            *reinterpret_cast<float4*>(&sm[B_WE2 + j * EPAD + k]) = se[i];
        }
        if (tid < 128) sm[B_C + tid] = g_c[tid];
        if (tid < 64) {
            sm[B_P + tid]   = We1[2 * tid];
            sm[B_Q + tid]   = We1[2 * tid + 1];
            sm[B_BE1 + tid] = be1[tid];
            sm[B_BE2 + tid] = be2[tid];
            sm[B_W3 + tid]  = We3[tid];
        }
        if (tid == 0) sm[B_D0] = g_c[PP];
    }
    __syncthreads();

    const int w    = tid >> 5;
    const int lane = tid & 31;
    float* E1 = sm + B_E + w * 768;
    const int base_pt = blockIdx.x * WARPS + w;
    const float c0 = sm[B_C + lane], c1 = sm[B_C + lane + 32];
    const float c2 = sm[B_C + lane + 64], c3 = sm[B_C + lane + 96];
    const float d0 = sm[B_D0];

    for (int it = 0; it < ITERS_B; ++it) {
        const int pt = base_pt + it * STRIDE_B;
        const bool active = pt < NXP;

        float p0, p1, p2, p3;
        {
            float4 j0, j1, j2, j3;
            if (active) {
                j0 = g_jets[pt][lane];      j1 = g_jets[pt][lane + 32];
                j2 = g_jets[pt][lane + 64]; j3 = g_jets[pt][lane + 96];
            } else {
                j0 = j1 = j2 = j3 = make_float4(0.f, 0.f, 0.f, 0.f);
            }
            p0 = c0 * j0.x + c1 * j1.x + c2 * j2.x + c3 * j3.x;
            p1 = c0 * j0.y + c1 * j1.y + c2 * j2.y + c3 * j3.y;
            p2 = c0 * j0.z + c1 * j1.z + c2 * j2.z + c3 * j3.z;
            p3 = c0 * j0.w + c1 * j1.w + c2 * j2.w + c3 * j3.w;
        }
#pragma unroll
        for (int o = 16; o; o >>= 1) {
            p0 += __shfl_xor_sync(0xffffffffu, p0, o);
            p1 += __shfl_xor_sync(0xffffffffu, p1, o);
            p2 += __shfl_xor_sync(0xffffffffu, p2, o);
            p3 += __shfl_xor_sync(0xffffffffu, p3, o);
        }
        const float u0 = p0 + d0, u1 = p1, u2 = p2, u3 = p3;

#pragma unroll
        for (int m = 0; m < 2; ++m) {
            int e = lane + 32 * m;
            float pp = sm[B_P + e], qq = sm[B_Q + e];
            float T, s, d2, d3;
            jet3(pp * u0 + qq * u1 + sm[B_BE1 + e], T, s, d2, d3);
            float* eb = &E1[12 * e];
            *reinterpret_cast<float4*>(eb) = make_float4(T, s * pp, s * qq, d2 * pp * pp);
            *reinterpret_cast<float4*>(eb + 4) =
                make_float4(d2 * pp * qq, d2 * qq * qq, d3 * pp * pp * qq, d3 * pp * qq * qq);
            eb[8] = d3 * qq * qq * qq;
        }
        __syncwarp();

        float b[2][9];
#pragma unroll
        for (int m = 0; m < 2; ++m)
#pragma unroll
            for (int s9 = 0; s9 < 9; ++s9) b[m][s9] = 0.f;
#pragma unroll 4
        for (int k4 = 0; k4 < 16; ++k4) {
            float4 wv0 = *reinterpret_cast<const float4*>(&sm[B_WE2 + lane * EPAD + 4 * k4]);
            float4 wv1 = *reinterpret_cast<const float4*>(&sm[B_WE2 + (lane + 32) * EPAD + 4 * k4]);
#pragma unroll
            for (int i = 0; i < 4; ++i) {
                const float* e = &E1[12 * (4 * k4 + i)];
                float4 eA = *reinterpret_cast<const float4*>(e);
                float4 eB = *reinterpret_cast<const float4*>(e + 4);
                float  eC = e[8];
                float wk0 = (i == 0) ? wv0.x : (i == 1) ? wv0.y : (i == 2) ? wv0.z : wv0.w;
                float wk1 = (i == 0) ? wv1.x : (i == 1) ? wv1.y : (i == 2) ? wv1.z : wv1.w;
                b[0][0] += wk0 * eA.x; b[0][1] += wk0 * eA.y; b[0][2] += wk0 * eA.z; b[0][3] += wk0 * eA.w;
                b[0][4] += wk0 * eB.x; b[0][5] += wk0 * eB.y; b[0][6] += wk0 * eB.z; b[0][7] += wk0 * eB.w;
                b[0][8] += wk0 * eC;
                b[1][0] += wk1 * eA.x; b[1][1] += wk1 * eA.y; b[1][2] += wk1 * eA.z; b[1][3] += wk1 * eA.w;
                b[1][4] += wk1 * eB.x; b[1][5] += wk1 * eB.y; b[1][6] += wk1 * eB.z; b[1][7] += wk1 * eB.w;
                b[1][8] += wk1 * eC;
            }
        }

        float q0 = 0.f, q1 = 0.f, q2 = 0.f, q3 = 0.f, q4 = 0.f;
#pragma unroll
        for (int m = 0; m < 2; ++m) {
            int o = lane + 32 * m;
            float az0  = b[m][0] + sm[B_BE2 + o];
            float ay   = b[m][1], az   = b[m][2];
            float ayy  = b[m][3], ayz  = b[m][4], azz = b[m][5];
            float ayyz = b[m][6], ayzz = b[m][7], azzz = b[m][8];
            float T, s, d2, d3;
            jet3(az0, T, s, d2, d3);
            float vyy  = s * ayy  + d2 * ay * ay;
            float vzz  = s * azz  + d2 * az * az;
            float vyyz = s * ayyz + d2 * (ayy * az + 2.f * ayz * ay) + d3 * ay * ay * az;
            float vyzz = s * ayzz + d2 * (azz * ay + 2.f * ayz * az) + d3 * ay * az * az;
            float vzzz = s * azzz + 3.f * d2 * azz * az + d3 * az * az * az;
            float w3 = sm[B_W3 + o];
            q0 += w3 * vyy; q1 += w3 * vzz; q2 += w3 * vyyz; q3 += w3 * vyzz; q4 += w3 * vzzz;
        }
#pragma unroll
        for (int o = 16; o; o >>= 1) {
            q0 += __shfl_xor_sync(0xffffffffu, q0, o);
            q1 += __shfl_xor_sync(0xffffffffu, q1, o);
            q2 += __shfl_xor_sync(0xffffffffu, q2, o);
            q3 += __shfl_xor_sync(0xffffffffu, q3, o);
            q4 += __shfl_xor_sync(0xffffffffu, q4, o);
        }
        if (lane == 0 && active) {
            out[pt] = -q0 * u1 + q1 * u3 + q2 * u1 * u1
                    + 2.f * q3 * u1 * u2 + q4 * u2 * u2;
        }
        __syncwarp();
    }
}

// ---------------------------------------------------------------- launch
extern "C" void kernel_launch(void* const* d_in, const int* in_sizes, int n_in,
                              void* d_out, int out_size) {
    const float* a   = (const float*)d_in[0];
    const float* x   = (const float*)d_in[1];
    const float* t   = (const float*)d_in[2];
    const float* Wb  = (const float*)d_in[3];
    const float* bb  = (const float*)d_in[4];
    const float* Wt1 = (const float*)d_in[5];
    const float* bt1 = (const float*)d_in[6];
    const float* Wt2 = (const float*)d_in[7];
    const float* bt2 = (const float*)d_in[8];
    const float* Wt3 = (const float*)d_in[9];
    const float* bt3 = (const float*)d_in[10];
    const float* We1 = (const float*)d_in[11];
    const float* be1 = (const float*)d_in[12];
    const float* We2 = (const float*)d_in[13];
    const float* be2 = (const float*)d_in[14];
    const float* We3 = (const float*)d_in[15];
    (void)in_sizes; (void)n_in;
    float* out = (float*)d_out; (void)out_size;

    size_t smemA = A_SMEM_FLOATS * sizeof(float);
    cudaFuncSetAttribute(k_A, cudaFuncAttributeMaxDynamicSharedMemorySize, (int)smemA);
    k_A<<<GRID_A, TPB_A, smemA>>>(Wb, a, x, t, Wt1, bt1, Wt2, bt2);

    k_coeff<<<1, 128>>>(Wt3, bt3, bb);

    size_t smemB = B_SMEM * sizeof(float);
    cudaFuncSetAttribute(k_B, cudaFuncAttributeMaxDynamicSharedMemorySize, (int)smemB);
    k_B<<<GRID_B, TPB, smemB>>>(We1, be1, We2, be2, We3, out);
}